// round 1
// baseline (speedup 1.0000x reference)
#include <cuda_runtime.h>
#include <math.h>

// ---------------- problem constants ----------------
#define BB 2
#define LL 1024
#define DM 512
#define DI 1024
#define RK 32
#define NS 16
#define MTOK (BB*LL)          // 2048 tokens

// ---------------- scratch (static device arrays; no dynamic alloc) ---------
__device__ __align__(16) float g_xz[MTOK * 2 * DI];     // in_proj output [2048,2048]
__device__ __align__(16) float g_xs[MTOK * DI];         // silu(conv1d)   [2048,1024]
__device__ __align__(16) float g_dBC[MTOK * 64];        // x_proj output  [2048,64]
__device__ __align__(16) float g_delta[MTOK * DI];      // softplus(dt)   [2048,1024]
__device__ __align__(16) float g_yg[MTOK * DI];         // y * silu(z)    [2048,1024]
__device__ __align__(16) float g_negA[DI * NS];         // -exp(A_log)

// ---------------- helpers ----------------
union F2 { unsigned long long u; float2 f; };

__device__ __forceinline__ void ffma2(F2& d, const F2& a, const F2& b) {
    // packed fp32x2 FMA (Blackwell): 2 FMAs per issue slot
    asm("fma.rn.f32x2 %0, %1, %2, %0;" : "+l"(d.u) : "l"(a.u), "l"(b.u));
}

__device__ __forceinline__ float softplusf(float v) {
    return (v > 20.f) ? v : log1pf(expf(v));
}

__device__ __forceinline__ float siluf(float v) {
    return v / (1.f + __expf(-v));
}

// ---------------- generic NT GEMM: C[M,N] = A[M,K] * B[N,K]^T --------------
// EPI: 0 = plain store, 1 = softplus(acc + bias[col])
template<int BM, int BN, int BK, int TM, int TN, int EPI>
__global__ void __launch_bounds__((BM/TM)*(BN/TN))
gemm_nt(const float* __restrict__ A, const float* __restrict__ B,
        float* __restrict__ C, int M, int N, int K,
        int lda, int ldb, int ldc, const float* __restrict__ bias)
{
    constexpr int THREADS = (BM/TM) * (BN/TN);
    constexpr int TXN = BN / TN;
    __shared__ __align__(16) float As[BK][BM];
    __shared__ __align__(16) float Bs[BK][BN];

    const int tid = threadIdx.x;
    const int tx  = tid % TXN;
    const int ty  = tid / TXN;
    const int row0 = blockIdx.y * BM;
    const int col0 = blockIdx.x * BN;

    F2 acc[TM][TN/2];
    #pragma unroll
    for (int i = 0; i < TM; i++)
        #pragma unroll
        for (int j = 0; j < TN/2; j++) { acc[i][j].f.x = 0.f; acc[i][j].f.y = 0.f; }

    for (int k0 = 0; k0 < K; k0 += BK) {
        for (int i = tid; i < BM*BK/4; i += THREADS) {
            int r = i / (BK/4), cv = i % (BK/4);
            float4 v = *reinterpret_cast<const float4*>(
                &A[(size_t)(row0 + r) * lda + k0 + cv*4]);
            As[cv*4+0][r] = v.x; As[cv*4+1][r] = v.y;
            As[cv*4+2][r] = v.z; As[cv*4+3][r] = v.w;
        }
        for (int i = tid; i < BN*BK/4; i += THREADS) {
            int r = i / (BK/4), cv = i % (BK/4);
            float4 v = *reinterpret_cast<const float4*>(
                &B[(size_t)(col0 + r) * ldb + k0 + cv*4]);
            Bs[cv*4+0][r] = v.x; Bs[cv*4+1][r] = v.y;
            Bs[cv*4+2][r] = v.z; Bs[cv*4+3][r] = v.w;
        }
        __syncthreads();

        #pragma unroll
        for (int k = 0; k < BK; k++) {
            float a_frag[TM];
            F2 b_frag[TN/2];
            #pragma unroll
            for (int i = 0; i < TM; i++) a_frag[i] = As[k][ty*TM + i];
            #pragma unroll
            for (int j = 0; j < TN/2; j++)
                b_frag[j] = *reinterpret_cast<const F2*>(&Bs[k][tx*TN + 2*j]);
            #pragma unroll
            for (int i = 0; i < TM; i++) {
                F2 ad; ad.f.x = a_frag[i]; ad.f.y = a_frag[i];
                #pragma unroll
                for (int j = 0; j < TN/2; j++) ffma2(acc[i][j], ad, b_frag[j]);
            }
        }
        __syncthreads();
    }

    #pragma unroll
    for (int i = 0; i < TM; i++) {
        int r = row0 + ty*TM + i;
        #pragma unroll
        for (int j = 0; j < TN/2; j++) {
            int c = col0 + tx*TN + 2*j;
            float2 v = acc[i][j].f;
            if (EPI == 1) {
                v.x = softplusf(v.x + bias[c]);
                v.y = softplusf(v.y + bias[c+1]);
            }
            *reinterpret_cast<float2*>(&C[(size_t)r * ldc + c]) = v;
        }
    }
}

// ---------------- negA precompute ----------------
__global__ void negA_kernel(const float* __restrict__ A_log) {
    int i = blockIdx.x * blockDim.x + threadIdx.x;
    if (i < DI * NS) g_negA[i] = -expf(A_log[i]);
}

// ---------------- depthwise conv1d (K=3, SAME) + silu ----------------
__global__ void conv_silu_kernel(const float* __restrict__ w,
                                 const float* __restrict__ b)
{
    int d = blockIdx.x * blockDim.x + threadIdx.x;   // 0..1023
    int m = blockIdx.y;                               // 0..2047
    int l = m & (LL - 1);
    float w0 = w[d*3+0], w1 = w[d*3+1], w2 = w[d*3+2];
    float xm = (l > 0)      ? g_xz[(size_t)(m-1)*2*DI + d] : 0.f;
    float x0 =                g_xz[(size_t)m    *2*DI + d];
    float xp = (l < LL-1)   ? g_xz[(size_t)(m+1)*2*DI + d] : 0.f;
    float v = fmaf(w0, xm, fmaf(w1, x0, fmaf(w2, xp, b[d])));
    g_xs[(size_t)m*DI + d] = siluf(v);
}

// ---------------- fused SSM + state-fusion + y + gate ----------------
__global__ void ssm_fused_kernel(const float* __restrict__ h,
                                 const float* __restrict__ Dvec,
                                 const float* __restrict__ sf1w,
                                 const float* __restrict__ sf1b,
                                 const float* __restrict__ sf2w,
                                 const float* __restrict__ sf2b,
                                 const float* __restrict__ alpha,
                                 float* __restrict__ out_hn)
{
    int d = blockIdx.x * blockDim.x + threadIdx.x;   // 0..1023
    int m = blockIdx.y;                               // 0..2047
    size_t md = (size_t)m * DI + d;

    float dv  = g_delta[md];
    float xsv = g_xs[md];
    float dx  = dv * xsv;
    const float* dbc = g_dBC + (size_t)m * 64;

    // hn = exp(delta*A)*h + (delta*xs)*B
    const float4* hp = reinterpret_cast<const float4*>(h + md * NS);
    float hn[16];
    #pragma unroll
    for (int q = 0; q < 4; q++) {
        float4 hv = hp[q];
        float na0 = g_negA[d*NS + 4*q + 0];
        float na1 = g_negA[d*NS + 4*q + 1];
        float na2 = g_negA[d*NS + 4*q + 2];
        float na3 = g_negA[d*NS + 4*q + 3];
        hn[4*q+0] = fmaf(__expf(dv*na0), hv.x, dx * dbc[32 + 4*q + 0]);
        hn[4*q+1] = fmaf(__expf(dv*na1), hv.y, dx * dbc[32 + 4*q + 1]);
        hn[4*q+2] = fmaf(__expf(dv*na2), hv.z, dx * dbc[32 + 4*q + 2]);
        hn[4*q+3] = fmaf(__expf(dv*na3), hv.w, dx * dbc[32 + 4*q + 3]);
    }

    // state fusion: alpha0*(1x1) + alpha1*(3x3, pad 1) on 4x4 grid
    float a0 = alpha[0], a1 = alpha[1];
    float c1 = a0 * sf1w[d];
    float cb = fmaf(a0, sf1b[d], a1 * sf2b[d]);
    float w[9];
    #pragma unroll
    for (int i = 0; i < 9; i++) w[i] = sf2w[d*9 + i];

    float y = 0.f;
    float hf[16];
    #pragma unroll
    for (int r = 0; r < 4; r++) {
        #pragma unroll
        for (int c = 0; c < 4; c++) {
            float acc = 0.f;
            #pragma unroll
            for (int ii = 0; ii < 3; ii++) {
                int rr = r + ii - 1;
                if (rr < 0 || rr > 3) continue;
                #pragma unroll
                for (int jj = 0; jj < 3; jj++) {
                    int cc = c + jj - 1;
                    if (cc < 0 || cc > 3) continue;
                    acc = fmaf(w[ii*3 + jj], hn[rr*4 + cc], acc);
                }
            }
            float v = fmaf(c1, hn[r*4 + c], fmaf(a1, acc, cb));
            hf[r*4 + c] = v;
            y = fmaf(v, dbc[48 + r*4 + c], y);
        }
    }

    // write fused hn (second output region)
    float4* op = reinterpret_cast<float4*>(out_hn + md * NS);
    #pragma unroll
    for (int q = 0; q < 4; q++)
        op[q] = make_float4(hf[4*q+0], hf[4*q+1], hf[4*q+2], hf[4*q+3]);

    // y = einsum + D*xs, then gate with silu(z)
    y = fmaf(Dvec[d], xsv, y);
    float zv = g_xz[(size_t)m * 2 * DI + DI + d];
    g_yg[md] = y * siluf(zv);
}

// ---------------- launch ----------------
extern "C" void kernel_launch(void* const* d_in, const int* in_sizes, int n_in,
                              void* d_out, int out_size)
{
    const float* x          = (const float*)d_in[0];
    const float* h          = (const float*)d_in[1];
    const float* in_proj_w  = (const float*)d_in[2];
    const float* conv1d_w   = (const float*)d_in[3];
    const float* conv1d_b   = (const float*)d_in[4];
    const float* x_proj_w   = (const float*)d_in[5];
    const float* dt_proj_w  = (const float*)d_in[6];
    const float* dt_proj_b  = (const float*)d_in[7];
    const float* A_log      = (const float*)d_in[8];
    const float* Dvec       = (const float*)d_in[9];
    const float* sf1_w      = (const float*)d_in[10];
    const float* sf1_b      = (const float*)d_in[11];
    const float* sf2_w      = (const float*)d_in[12];
    const float* sf2_b      = (const float*)d_in[13];
    const float* alpha      = (const float*)d_in[14];
    const float* out_proj_w = (const float*)d_in[15];

    float* out    = (float*)d_out;                    // [2048, 512]
    float* out_hn = (float*)d_out + (size_t)MTOK*DM;  // [2048, 1024, 16]

    float *xz, *xs, *dbc, *delta, *yg;
    cudaGetSymbolAddress((void**)&xz,    g_xz);
    cudaGetSymbolAddress((void**)&xs,    g_xs);
    cudaGetSymbolAddress((void**)&dbc,   g_dBC);
    cudaGetSymbolAddress((void**)&delta, g_delta);
    cudaGetSymbolAddress((void**)&yg,    g_yg);

    // negA precompute (tiny)
    negA_kernel<<<64, 256>>>(A_log);

    // K1: xz = x @ in_proj_w^T   [2048,2048,K=512]
    gemm_nt<128,128,16,8,8,0><<<dim3(16,16), 256>>>(
        x, in_proj_w, xz, MTOK, 2*DI, DM, DM, DM, 2*DI, nullptr);

    // K2: xs = silu(dwconv1d(xc))
    conv_silu_kernel<<<dim3(4, MTOK), 256>>>(conv1d_w, conv1d_b);

    // K3: dBC = xs @ x_proj_w^T  [2048,64,K=1024]  (skinny-N: BM=16 for parallelism)
    gemm_nt<16,64,32,1,4,0><<<dim3(1,128), 256>>>(
        xs, x_proj_w, dbc, MTOK, 64, DI, DI, DI, 64, nullptr);

    // K4: delta = softplus(dBC[:, :32] @ dt_proj_w^T + b)  [2048,1024,K=32]
    gemm_nt<64,64,16,4,4,1><<<dim3(16,32), 256>>>(
        dbc, dt_proj_w, delta, MTOK, DI, RK, 64, RK, DI, dt_proj_b);

    // K5: fused SSM + state fusion + y + gate; writes hn to d_out region 2
    ssm_fused_kernel<<<dim3(4, MTOK), 256>>>(
        h, Dvec, sf1_w, sf1_b, sf2_w, sf2_b, alpha, out_hn);

    // K6: out = (y * silu(z)) @ out_proj_w^T  [2048,512,K=1024]
    gemm_nt<64,64,16,4,4,0><<<dim3(8,32), 256>>>(
        yg, out_proj_w, out, MTOK, DM, DI, DI, DI, DM, nullptr);
}